// round 1
// baseline (speedup 1.0000x reference)
#include <cuda_runtime.h>
#include <cstdint>
#include <math.h>

#define TOK 32768
#define HDIM 1152
#define LHD 1152
#define HHD 4608

#define BM 128
#define BN 128
#define BK 32
#define LDSS 36   // padded row stride in floats (conflict-free: (4g+tg) mod 32 permutation)

// Scratch (allocation-free rule: __device__ globals)
__device__ float g_hl[(size_t)TOK * LHD];     // light fc1 activations
__device__ float g_hh[(size_t)TOK * HHD];     // heavy fc1 activations
__device__ float g_probs[TOK * 2];            // router softmax

__device__ __forceinline__ unsigned cvt_tf32(float x) {
    unsigned r;
    asm("cvt.rna.tf32.f32 %0, %1;" : "=r"(r) : "f"(x));
    return r;
}

__device__ __forceinline__ void cp_async16(uint32_t saddr, const void* gaddr) {
    asm volatile("cp.async.cg.shared.global [%0], [%1], 16;" :: "r"(saddr), "l"(gaddr));
}

__device__ __forceinline__ float gelu_exact(float v) {
    return 0.5f * v * (1.0f + erff(v * 0.70710678118654752f));
}

// ---------------------------------------------------------------------------
// Router: logits = x @ router_w^T + b; softmax over 2 experts.
// One warp per token.
// ---------------------------------------------------------------------------
__global__ void router_kernel(const float* __restrict__ x,
                              const float* __restrict__ rw,
                              const float* __restrict__ rb,
                              float* __restrict__ probs) {
    int t = blockIdx.x * 8 + (threadIdx.x >> 5);
    int lane = threadIdx.x & 31;
    const float* xt = x + (size_t)t * HDIM;
    float l0 = 0.f, l1 = 0.f;
    #pragma unroll 4
    for (int i = lane; i < HDIM; i += 32) {
        float v = xt[i];
        l0 += v * rw[i];
        l1 += v * rw[HDIM + i];
    }
    #pragma unroll
    for (int o = 16; o; o >>= 1) {
        l0 += __shfl_xor_sync(0xFFFFFFFFu, l0, o);
        l1 += __shfl_xor_sync(0xFFFFFFFFu, l1, o);
    }
    if (lane == 0) {
        l0 += rb[0];
        l1 += rb[1];
        float m = fmaxf(l0, l1);
        float e0 = expf(l0 - m), e1 = expf(l1 - m);
        float s = 1.0f / (e0 + e1);
        probs[t * 2 + 0] = e0 * s;
        probs[t * 2 + 1] = e1 * s;
    }
}

// ---------------------------------------------------------------------------
// TF32 GEMM: C[M,N] = epilogue( A[M,K] * B[N,K]^T + bias[N] )
// MODE 0: C = gelu(acc + bias)                      (fc1)
// MODE 1: C = p[row]*(acc + bias)                   (fc2 light, writes out)
// MODE 2: C = C + p[row]*(acc + bias)               (fc2 heavy, accumulates)
// Block 128x128x32, 8 warps (2x4), warp tile 64x32, mma.m16n8k8.tf32.
// Dims must divide tiles exactly (they do for this problem).
// ---------------------------------------------------------------------------
template <int MODE>
__global__ void __launch_bounds__(256, 2)
gemm_tf32(const float* __restrict__ A, const float* __restrict__ B,
          const float* __restrict__ bias, const float* __restrict__ probs,
          float* __restrict__ C, int M, int N, int K, int pidx) {
    extern __shared__ float smem[];
    float* As = smem;                       // [2][BM*LDSS]
    float* Bs = smem + 2 * BM * LDSS;       // [2][BN*LDSS]

    const int tid = threadIdx.x;
    const int warp = tid >> 5;
    const int lane = tid & 31;
    const int g = lane >> 2;     // group id (0..7)
    const int tg = lane & 3;     // thread-in-group (0..3)
    const int wm = (warp >> 2) * 64;   // warp m offset (0/64)
    const int wn = (warp & 3) * 32;    // warp n offset (0/32/64/96)

    const int mBase = blockIdx.y * BM;
    const int nBase = blockIdx.x * BN;

    uint32_t sA = (uint32_t)__cvta_generic_to_shared(As);
    uint32_t sB = (uint32_t)__cvta_generic_to_shared(Bs);

    // global->smem copy mapping: each thread copies 4x 16B per tile per matrix
    const int rowL = tid >> 3;          // 0..31
    const int c4 = (tid & 7) * 4;       // float offset in row (0,4,...,28)
    const float* gA = A + (size_t)(mBase + rowL) * K + c4;
    const float* gB = B + (size_t)(nBase + rowL) * K + c4;
    const uint32_t soff = (uint32_t)(rowL * LDSS + c4) * 4u;
    const uint32_t bufBytes = (uint32_t)(BM * LDSS) * 4u;

    float acc[4][4][4];
    #pragma unroll
    for (int mi = 0; mi < 4; mi++)
        #pragma unroll
        for (int ni = 0; ni < 4; ni++)
            #pragma unroll
            for (int j = 0; j < 4; j++) acc[mi][ni][j] = 0.f;

    const int KT = K / BK;

    // issue loads for tile k0 into buffer b
    auto issue = [&](int k0, int b) {
        uint32_t dA = sA + (uint32_t)b * bufBytes + soff;
        uint32_t dB = sB + (uint32_t)b * bufBytes + soff;
        #pragma unroll
        for (int it = 0; it < 4; it++) {
            cp_async16(dA + (uint32_t)(it * 32 * LDSS) * 4u, gA + (size_t)(it * 32) * K + k0);
            cp_async16(dB + (uint32_t)(it * 32 * LDSS) * 4u, gB + (size_t)(it * 32) * K + k0);
        }
        asm volatile("cp.async.commit_group;");
    };

    issue(0, 0);
    int buf = 0;

    for (int kt = 0; kt < KT; kt++) {
        if (kt + 1 < KT) {
            issue((kt + 1) * BK, buf ^ 1);
            asm volatile("cp.async.wait_group 1;");
        } else {
            asm volatile("cp.async.wait_group 0;");
        }
        __syncthreads();

        const float* Ab = As + buf * BM * LDSS;
        const float* Bb = Bs + buf * BM * LDSS;

        #pragma unroll
        for (int ks = 0; ks < 4; ks++) {
            const int kb = ks * 8;
            unsigned af[4][4], bf[4][2];
            #pragma unroll
            for (int mi = 0; mi < 4; mi++) {
                int r = wm + mi * 16 + g;
                af[mi][0] = cvt_tf32(Ab[r * LDSS + kb + tg]);
                af[mi][1] = cvt_tf32(Ab[(r + 8) * LDSS + kb + tg]);
                af[mi][2] = cvt_tf32(Ab[r * LDSS + kb + tg + 4]);
                af[mi][3] = cvt_tf32(Ab[(r + 8) * LDSS + kb + tg + 4]);
            }
            #pragma unroll
            for (int ni = 0; ni < 4; ni++) {
                int c = wn + ni * 8 + g;
                bf[ni][0] = cvt_tf32(Bb[c * LDSS + kb + tg]);
                bf[ni][1] = cvt_tf32(Bb[c * LDSS + kb + tg + 4]);
            }
            #pragma unroll
            for (int mi = 0; mi < 4; mi++) {
                #pragma unroll
                for (int ni = 0; ni < 4; ni++) {
                    asm volatile(
                        "mma.sync.aligned.m16n8k8.row.col.f32.tf32.tf32.f32 "
                        "{%0,%1,%2,%3}, {%4,%5,%6,%7}, {%8,%9}, {%0,%1,%2,%3};"
                        : "+f"(acc[mi][ni][0]), "+f"(acc[mi][ni][1]),
                          "+f"(acc[mi][ni][2]), "+f"(acc[mi][ni][3])
                        : "r"(af[mi][0]), "r"(af[mi][1]), "r"(af[mi][2]), "r"(af[mi][3]),
                          "r"(bf[ni][0]), "r"(bf[ni][1]));
                }
            }
        }
        __syncthreads();   // before next iter overwrites this buffer via cp.async
        buf ^= 1;
    }

    // -------- epilogue --------
    #pragma unroll
    for (int mi = 0; mi < 4; mi++) {
        int row = mBase + wm + mi * 16 + g;
        float p0r = 0.f, p1r = 0.f;
        if (MODE == 1 || MODE == 2) {
            p0r = probs[row * 2 + pidx];
            p1r = probs[(row + 8) * 2 + pidx];
        }
        #pragma unroll
        for (int ni = 0; ni < 4; ni++) {
            int col = nBase + wn + ni * 8 + tg * 2;
            float b0 = bias[col], b1 = bias[col + 1];
            float v00 = acc[mi][ni][0] + b0;
            float v01 = acc[mi][ni][1] + b1;
            float v10 = acc[mi][ni][2] + b0;
            float v11 = acc[mi][ni][3] + b1;

            float2* p0 = (float2*)(C + (size_t)row * N + col);
            float2* p1 = (float2*)(C + (size_t)(row + 8) * N + col);

            if (MODE == 0) {
                *p0 = make_float2(gelu_exact(v00), gelu_exact(v01));
                *p1 = make_float2(gelu_exact(v10), gelu_exact(v11));
            } else if (MODE == 1) {
                *p0 = make_float2(p0r * v00, p0r * v01);
                *p1 = make_float2(p1r * v10, p1r * v11);
            } else {
                float2 o0 = *p0, o1 = *p1;
                *p0 = make_float2(o0.x + p0r * v00, o0.y + p0r * v01);
                *p1 = make_float2(o1.x + p1r * v10, o1.y + p1r * v11);
            }
        }
    }
}

// ---------------------------------------------------------------------------
extern "C" void kernel_launch(void* const* d_in, const int* in_sizes, int n_in,
                              void* d_out, int out_size) {
    const float* x   = (const float*)d_in[0];
    const float* rw  = (const float*)d_in[1];
    const float* rb  = (const float*)d_in[2];
    const float* lw1 = (const float*)d_in[3];
    const float* lb1 = (const float*)d_in[4];
    const float* lw2 = (const float*)d_in[5];
    const float* lb2 = (const float*)d_in[6];
    const float* hw1 = (const float*)d_in[7];
    const float* hb1 = (const float*)d_in[8];
    const float* hw2 = (const float*)d_in[9];
    const float* hb2 = (const float*)d_in[10];
    float* out = (float*)d_out;

    float *hl, *hh, *probs;
    cudaGetSymbolAddress((void**)&hl, g_hl);
    cudaGetSymbolAddress((void**)&hh, g_hh);
    cudaGetSymbolAddress((void**)&probs, g_probs);

    const int SMEM = 2 * 2 * BM * LDSS * 4;  // 73728 bytes
    cudaFuncSetAttribute((const void*)gemm_tf32<0>, cudaFuncAttributeMaxDynamicSharedMemorySize, SMEM);
    cudaFuncSetAttribute((const void*)gemm_tf32<1>, cudaFuncAttributeMaxDynamicSharedMemorySize, SMEM);
    cudaFuncSetAttribute((const void*)gemm_tf32<2>, cudaFuncAttributeMaxDynamicSharedMemorySize, SMEM);

    router_kernel<<<TOK / 8, 256>>>(x, rw, rb, probs);

    dim3 blk(256);
    // fc1 light: hl = gelu(x @ lw1^T + lb1)   [M=TOK, N=1152, K=1152]
    gemm_tf32<0><<<dim3(LHD / BN, TOK / BM), blk, SMEM>>>(x, lw1, lb1, nullptr, hl, TOK, LHD, HDIM, 0);
    // fc1 heavy: hh = gelu(x @ hw1^T + hb1)   [M=TOK, N=4608, K=1152]
    gemm_tf32<0><<<dim3(HHD / BN, TOK / BM), blk, SMEM>>>(x, hw1, hb1, nullptr, hh, TOK, HHD, HDIM, 0);
    // fc2 light: out = p0 * (hl @ lw2^T + lb2)   [M=TOK, N=1152, K=1152]
    gemm_tf32<1><<<dim3(HDIM / BN, TOK / BM), blk, SMEM>>>(hl, lw2, lb2, probs, out, TOK, HDIM, LHD, 0);
    // fc2 heavy: out += p1 * (hh @ hw2^T + hb2)  [M=TOK, N=1152, K=4608]
    gemm_tf32<2><<<dim3(HDIM / BN, TOK / BM), blk, SMEM>>>(hh, hw2, hb2, probs, out, TOK, HDIM, HHD, 1);
}

// round 4
// speedup vs baseline: 2.1646x; 2.1646x over previous
#include <cuda_runtime.h>
#include <cuda_fp16.h>
#include <cstdint>
#include <math.h>

#define TOK 32768
#define HDIM 1152
#define LHD 1152
#define HHD 4608
#define BM 128
#define BN 128
#define BK 64

// ---------------- device scratch (allocation-free rule) ----------------
__device__ __half g_xh[(size_t)TOK * HDIM];
__device__ __half g_hl[(size_t)TOK * LHD];
__device__ __half g_hh[(size_t)TOK * HHD];
__device__ float  g_probs[TOK * 2];
__device__ __half g_w1l[(size_t)LHD * HDIM];
__device__ __half g_w2l[(size_t)HDIM * LHD];
__device__ __half g_w1h[(size_t)HHD * HDIM];
__device__ __half g_w2h[(size_t)HDIM * HHD];

// ---------------- helpers ----------------
__device__ __forceinline__ float gelu_exact(float v) {
    return 0.5f * v * (1.0f + erff(v * 0.70710678118654752f));
}
__device__ __forceinline__ void cp_async16(uint32_t saddr, const void* gaddr) {
    asm volatile("cp.async.cg.shared.global [%0], [%1], 16;" :: "r"(saddr), "l"(gaddr));
}
__device__ __forceinline__ uint32_t smem_u32(const void* p) {
    uint32_t a;
    asm("{ .reg .u64 t; cvta.to.shared.u64 t, %1; cvt.u32.u64 %0, t; }" : "=r"(a) : "l"(p));
    return a;
}
#define SWZ(o) ((o) ^ (((o) >> 3) & 0x70))

__device__ __forceinline__ void ldsm_x4(uint32_t& r0, uint32_t& r1, uint32_t& r2, uint32_t& r3,
                                        uint32_t saddr) {
    asm volatile("ldmatrix.sync.aligned.m8n8.x4.shared.b16 {%0,%1,%2,%3}, [%4];"
                 : "=r"(r0), "=r"(r1), "=r"(r2), "=r"(r3) : "r"(saddr));
}
__device__ __forceinline__ void mma_f16(float* d, const uint32_t* a, uint32_t b0, uint32_t b1) {
    asm volatile(
        "mma.sync.aligned.m16n8k16.row.col.f32.f16.f16.f32 "
        "{%0,%1,%2,%3}, {%4,%5,%6,%7}, {%8,%9}, {%0,%1,%2,%3};"
        : "+f"(d[0]), "+f"(d[1]), "+f"(d[2]), "+f"(d[3])
        : "r"(a[0]), "r"(a[1]), "r"(a[2]), "r"(a[3]), "r"(b0), "r"(b1));
}

// ---------------------------------------------------------------------------
// fp32 -> fp16 conversion (weights)
// ---------------------------------------------------------------------------
__global__ void cvt_h_kernel(const float* __restrict__ in, __half* __restrict__ out, int n4) {
    int i = blockIdx.x * 256 + threadIdx.x;
    if (i < n4) {
        float4 v = ((const float4*)in)[i];
        __half2 h0 = __floats2half2_rn(v.x, v.y);
        __half2 h1 = __floats2half2_rn(v.z, v.w);
        ((__half2*)out)[i * 2 + 0] = h0;
        ((__half2*)out)[i * 2 + 1] = h1;
    }
}

// ---------------------------------------------------------------------------
// Router (one warp per token) — also emits the fp16 copy of x.
// ---------------------------------------------------------------------------
__global__ void router_kernel(const float* __restrict__ x,
                              const float* __restrict__ rw,
                              const float* __restrict__ rb,
                              float* __restrict__ probs,
                              __half* __restrict__ xh) {
    int t = blockIdx.x * 8 + (threadIdx.x >> 5);
    int lane = threadIdx.x & 31;
    const float* xt = x + (size_t)t * HDIM;
    __half* xht = xh + (size_t)t * HDIM;
    float l0 = 0.f, l1 = 0.f;
    #pragma unroll 4
    for (int i = lane; i < HDIM; i += 32) {
        float v = xt[i];
        xht[i] = __float2half_rn(v);
        l0 += v * rw[i];
        l1 += v * rw[HDIM + i];
    }
    #pragma unroll
    for (int o = 16; o; o >>= 1) {
        l0 += __shfl_xor_sync(0xFFFFFFFFu, l0, o);
        l1 += __shfl_xor_sync(0xFFFFFFFFu, l1, o);
    }
    if (lane == 0) {
        l0 += rb[0];
        l1 += rb[1];
        float m = fmaxf(l0, l1);
        float e0 = expf(l0 - m), e1 = expf(l1 - m);
        float s = 1.0f / (e0 + e1);
        probs[t * 2 + 0] = e0 * s;
        probs[t * 2 + 1] = e1 * s;
    }
}

// ---------------------------------------------------------------------------
// fp16 GEMM: C[M,N] = epi( A[M,K] * B[N,K]^T + bias[N] )
//   MODE 0: C(half)  = half(gelu(v))     (fc1 -> scratch)
//   MODE 1: C(float) = p[row]*v          (fc2 light, writes out)
//   MODE 2: C(float) += p[row]*v         (fc2 heavy, accumulates out)
// 128x128x64 tiles, 8 warps (2x4), warp tile 64x32, mma.m16n8k16.f16,
// ldmatrix fragments, SW128 swizzle, 3-stage cp.async pipeline, 2 CTAs/SM.
// ---------------------------------------------------------------------------
template <int MODE>
__global__ void __launch_bounds__(256, 2)
gemm_h(const __half* __restrict__ A, const __half* __restrict__ B,
       const float* __restrict__ bias, const float* __restrict__ probs,
       void* __restrict__ Cv, int N, int K, int pidx) {
    constexpr int TILE = BM * BK * 2;       // 16384 B (one matrix, one stage)
    constexpr int STAGE = 2 * TILE;         // 32768 B
    extern __shared__ char smem_raw[];
    const uint32_t S0 = smem_u32(smem_raw);

    const int tid = threadIdx.x;
    const int warp = tid >> 5;
    const int lane = tid & 31;
    const int g = lane >> 2;
    const int tg = lane & 3;
    const int wm = (warp >> 2) * 64;
    const int wn = (warp & 3) * 32;
    const int mBase = blockIdx.y * BM;
    const int nBase = blockIdx.x * BN;
    const int KT = K / BK;

    // cp.async mapping: 1024 16B-chunks per matrix per stage, 4 per thread.
    const __half* Ag = A + (size_t)mBase * K;
    const __half* Bg = B + (size_t)nBase * K;

    auto issue = [&](int kt, int s) {
        const uint32_t stA = S0 + s * STAGE;
        const uint32_t stB = stA + TILE;
        const int k0 = kt * BK;
        #pragma unroll
        for (int it = 0; it < 4; it++) {
            int c = tid + it * 256;
            int row = c >> 3, col = c & 7;
            uint32_t so = SWZ(row * 128 + col * 16);
            cp_async16(stA + so, Ag + (size_t)row * K + k0 + col * 8);
            cp_async16(stB + so, Bg + (size_t)row * K + k0 + col * 8);
        }
        asm volatile("cp.async.commit_group;");
    };

    float acc[4][4][4];
    #pragma unroll
    for (int mi = 0; mi < 4; mi++)
        #pragma unroll
        for (int ni = 0; ni < 4; ni++)
            #pragma unroll
            for (int j = 0; j < 4; j++) acc[mi][ni][j] = 0.f;

    issue(0, 0);
    issue(1, 1);

    // ldmatrix lane address components (x4: lanes 0-15 rows, lanes 16-31 k+8)
    const int lmr = lane & 15;
    const int lmk = (lane >> 4) * 16;   // byte offset within row

    for (int kt = 0; kt < KT; kt++) {
        if (kt + 2 < KT) {
            issue(kt + 2, (kt + 2) % 3);
            asm volatile("cp.async.wait_group 2;");
        } else if (kt + 1 < KT) {
            asm volatile("cp.async.wait_group 1;");
        } else {
            asm volatile("cp.async.wait_group 0;");
        }
        __syncthreads();

        const uint32_t stA = S0 + (kt % 3) * STAGE;
        const uint32_t stB = stA + TILE;

        #pragma unroll
        for (int ks = 0; ks < 4; ks++) {
            const int kb = ks * 32;   // byte offset of this k16 chunk
            uint32_t af[4][4], bf[2][4];
            #pragma unroll
            for (int mi = 0; mi < 4; mi++)
                ldsm_x4(af[mi][0], af[mi][1], af[mi][2], af[mi][3],
                        stA + SWZ((wm + mi * 16 + lmr) * 128 + kb + lmk));
            #pragma unroll
            for (int np = 0; np < 2; np++)
                ldsm_x4(bf[np][0], bf[np][1], bf[np][2], bf[np][3],
                        stB + SWZ((wn + np * 16 + lmr) * 128 + kb + lmk));
            #pragma unroll
            for (int mi = 0; mi < 4; mi++) {
                mma_f16(acc[mi][0], af[mi], bf[0][0], bf[0][2]);
                mma_f16(acc[mi][1], af[mi], bf[0][1], bf[0][3]);
                mma_f16(acc[mi][2], af[mi], bf[1][0], bf[1][2]);
                mma_f16(acc[mi][3], af[mi], bf[1][1], bf[1][3]);
            }
        }
        __syncthreads();
    }

    // -------- epilogue --------
    #pragma unroll
    for (int mi = 0; mi < 4; mi++) {
        int row = mBase + wm + mi * 16 + g;
        float p0r = 0.f, p1r = 0.f;
        if (MODE) {
            p0r = probs[row * 2 + pidx];
            p1r = probs[(row + 8) * 2 + pidx];
        }
        #pragma unroll
        for (int ni = 0; ni < 4; ni++) {
            int col = nBase + wn + ni * 8 + tg * 2;
            float b0 = bias[col], b1 = bias[col + 1];
            float v00 = acc[mi][ni][0] + b0;
            float v01 = acc[mi][ni][1] + b1;
            float v10 = acc[mi][ni][2] + b0;
            float v11 = acc[mi][ni][3] + b1;
            if (MODE == 0) {
                __half* Ch = (__half*)Cv;
                *(__half2*)(Ch + (size_t)row * N + col) =
                    __floats2half2_rn(gelu_exact(v00), gelu_exact(v01));
                *(__half2*)(Ch + (size_t)(row + 8) * N + col) =
                    __floats2half2_rn(gelu_exact(v10), gelu_exact(v11));
            } else {
                float* Cf = (float*)Cv;
                float2* p0 = (float2*)(Cf + (size_t)row * N + col);
                float2* p1 = (float2*)(Cf + (size_t)(row + 8) * N + col);
                if (MODE == 1) {
                    *p0 = make_float2(p0r * v00, p0r * v01);
                    *p1 = make_float2(p1r * v10, p1r * v11);
                } else {
                    float2 o0 = *p0, o1 = *p1;
                    *p0 = make_float2(o0.x + p0r * v00, o0.y + p0r * v01);
                    *p1 = make_float2(o1.x + p1r * v10, o1.y + p1r * v11);
                }
            }
        }
    }
}

// ---------------------------------------------------------------------------
extern "C" void kernel_launch(void* const* d_in, const int* in_sizes, int n_in,
                              void* d_out, int out_size) {
    const float* x   = (const float*)d_in[0];
    const float* rw  = (const float*)d_in[1];
    const float* rb  = (const float*)d_in[2];
    const float* lw1 = (const float*)d_in[3];
    const float* lb1 = (const float*)d_in[4];
    const float* lw2 = (const float*)d_in[5];
    const float* lb2 = (const float*)d_in[6];
    const float* hw1 = (const float*)d_in[7];
    const float* hb1 = (const float*)d_in[8];
    const float* hw2 = (const float*)d_in[9];
    const float* hb2 = (const float*)d_in[10];
    float* out = (float*)d_out;

    __half *xh, *hl, *hh, *w1l, *w2l, *w1h, *w2h;
    float *probs;
    cudaGetSymbolAddress((void**)&xh, g_xh);
    cudaGetSymbolAddress((void**)&hl, g_hl);
    cudaGetSymbolAddress((void**)&hh, g_hh);
    cudaGetSymbolAddress((void**)&probs, g_probs);
    cudaGetSymbolAddress((void**)&w1l, g_w1l);
    cudaGetSymbolAddress((void**)&w2l, g_w2l);
    cudaGetSymbolAddress((void**)&w1h, g_w1h);
    cudaGetSymbolAddress((void**)&w2h, g_w2h);

    const int SMEM = 3 * 2 * BM * BK * 2;   // 98304 bytes
    cudaFuncSetAttribute((const void*)gemm_h<0>, cudaFuncAttributeMaxDynamicSharedMemorySize, SMEM);
    cudaFuncSetAttribute((const void*)gemm_h<1>, cudaFuncAttributeMaxDynamicSharedMemorySize, SMEM);
    cudaFuncSetAttribute((const void*)gemm_h<2>, cudaFuncAttributeMaxDynamicSharedMemorySize, SMEM);

    // fp16 weight copies
    int n1 = LHD * HDIM / 4, n2 = HHD * HDIM / 4;
    cvt_h_kernel<<<(n1 + 255) / 256, 256>>>(lw1, w1l, n1);
    cvt_h_kernel<<<(n1 + 255) / 256, 256>>>(lw2, w2l, n1);
    cvt_h_kernel<<<(n2 + 255) / 256, 256>>>(hw1, w1h, n2);
    cvt_h_kernel<<<(n2 + 255) / 256, 256>>>(hw2, w2h, n2);

    // router + x fp16
    router_kernel<<<TOK / 8, 256>>>(x, rw, rb, probs, xh);

    dim3 blk(256);
    // fc1 light: hl = h(gelu(xh @ w1l^T + lb1))   [M=32768, N=1152, K=1152]
    gemm_h<0><<<dim3(LHD / BN, TOK / BM), blk, SMEM>>>(xh, w1l, lb1, nullptr, hl, LHD, HDIM, 0);
    // fc1 heavy: hh = h(gelu(xh @ w1h^T + hb1))   [M=32768, N=4608, K=1152]
    gemm_h<0><<<dim3(HHD / BN, TOK / BM), blk, SMEM>>>(xh, w1h, hb1, nullptr, hh, HHD, HDIM, 0);
    // fc2 light: out = p0 * (hl @ w2l^T + lb2)    [M=32768, N=1152, K=1152]
    gemm_h<1><<<dim3(HDIM / BN, TOK / BM), blk, SMEM>>>(hl, w2l, lb2, probs, out, HDIM, LHD, 0);
    // fc2 heavy: out += p1 * (hh @ w2h^T + hb2)   [M=32768, N=1152, K=4608]
    gemm_h<2><<<dim3(HDIM / BN, TOK / BM), blk, SMEM>>>(hh, w2h, hb2, probs, out, HDIM, HHD, 1);
}